// round 10
// baseline (speedup 1.0000x reference)
#include <cuda_runtime.h>
#include <cstdint>

#define B_VAL 16
#define M_VAL 64
#define A_VAL 33600
#define BM_VAL (B_VAL * M_VAL)
#define BA_VAL (B_VAL * A_VAL)
#define NC 80
#define EPSV 1e-9f

#define SLAB_BYTES (256 * NC * 4)   // 81920 bytes of scores per block
#define ZBUF_BYTES 32768            // shared zero staging buffer

// Scratch: per-(b,anchor) positive count and (one) contributing gt index.
// Zero-initialized at module load; mega_kernel self-cleans g_pos_count after
// reading, so every launch (and graph replay) begins with a zeroed table.
__device__ int g_pos_count[BA_VAL];
__device__ int g_pos_gt[BA_VAL];

__device__ __forceinline__ uint32_t smem_u32(const void* p) {
    uint32_t a;
    asm("{ .reg .u64 t; cvta.to.shared.u64 t, %1; cvt.u32.u64 %0, t; }"
        : "=r"(a) : "l"(p));
    return a;
}

// ---------------------------------------------------------------------------
__device__ __forceinline__ void anchor_geom(int a, float& cx, float& cy, float& half) {
    int base, nside; float s;
    if (a < 25600)      { s = 8.f;  base = 0;     nside = 160; }
    else if (a < 32000) { s = 16.f; base = 25600; nside = 80;  }
    else                { s = 32.f; base = 32000; nside = 40;  }
    int loc = a - base;
    cx = ((loc % nside) + 0.5f) * s;
    cy = ((loc / nside) + 0.5f) * s;
    half = 2.5f * s;
}

__device__ __forceinline__ float iou_eval(float ax0, float ay0, float ax1, float ay1,
                                          float area_a,
                                          float gx0, float gy0, float gx1, float gy1) {
    float area_g = (gx1 - gx0) * (gy1 - gy0);
    float lx = fmaxf(gx0, ax0), ly = fmaxf(gy0, ay0);
    float rx = fminf(gx1, ax1), ry = fminf(gy1, ay1);
    float w = fmaxf(rx - lx, 0.f), h = fmaxf(ry - ly, 0.f);
    float ov = w * h;
    return ov / (area_g + area_a - ov + EPSV);
}

// ---------------------------------------------------------------------------
// Kernel 1 (warp-parallel, proven R8): ONE BLOCK (96 threads) per (b, m);
// warp = FPN level; 7x7 analytic window; 9 warp-min extractions on
// (d2_bits<<32)|p keys (lower-index tie-break preserved); canonical-order
// serial mean+std(ddof=1); center-in-gt; atomic scatter.
// ---------------------------------------------------------------------------
__global__ void __launch_bounds__(96) topk_assign_kernel(const float* __restrict__ gt_bboxes,
                                                         const float* __restrict__ pad_mask) {
    const int t = blockIdx.x;              // b*64 + m
    if (pad_mask[t] <= 0.f) return;

    const int b = t >> 6;
    const int m = t & 63;
    const int warp = threadIdx.x >> 5;     // level
    const int lane = threadIdx.x & 31;

    __shared__ int   s_idx[27];
    __shared__ float s_iou[27];
    __shared__ int   s_ok[27];
    __shared__ float s_thr;

    const float4 g = reinterpret_cast<const float4*>(gt_bboxes)[t];
    const float gx0 = g.x, gy0 = g.y, gx1 = g.z, gy1 = g.w;
    const float gcx = (gx0 + gx1) * 0.5f, gcy = (gy0 + gy1) * 0.5f;

    const int   base  = (warp == 0) ? 0     : (warp == 1) ? 25600 : 32000;
    const int   nside = (warp == 0) ? 160   : (warp == 1) ? 80    : 40;
    const float s     = (warp == 0) ? 8.f   : (warp == 1) ? 16.f  : 32.f;
    const float inv_s = (warp == 0) ? 0.125f : (warp == 1) ? 0.0625f : 0.03125f;

    int cn = (int)floorf(gcx * inv_s);
    int rn = (int)floorf(gcy * inv_s);
    int c0 = min(max(cn - 3, 0), nside - 7);
    int r0 = min(max(rn - 3, 0), nside - 7);

    auto cand_key = [&](int p) -> unsigned long long {
        int r = p / 7, c = p - r * 7;
        float cy = ((r0 + r) + 0.5f) * s;
        float cx = ((c0 + c) + 0.5f) * s;
        float dx = gcx - cx, dy = gcy - cy;
        float d2 = dx * dx + dy * dy;
        return ((unsigned long long)__float_as_uint(d2) << 32) | (unsigned)p;
    };

    const unsigned long long KMAX = ~0ULL;
    unsigned long long k0 = cand_key(lane);
    unsigned long long k1 = (lane + 32 < 49) ? cand_key(lane + 32) : KMAX;

#pragma unroll
    for (int round = 0; round < 9; round++) {
        unsigned long long local = (k0 < k1) ? k0 : k1;
        unsigned long long r = local;
#pragma unroll
        for (int off = 16; off > 0; off >>= 1) {
            unsigned long long o = __shfl_xor_sync(0xffffffffu, r, off);
            if (o < r) r = o;
        }
        if (local == r) {
            if (k0 == r) k0 = KMAX; else k1 = KMAX;
        }
        if (lane == 0) {
            int p = (int)(r & 0xffffffffu);
            int rr = p / 7, cc = p - rr * 7;
            s_idx[warp * 9 + round] = base + (r0 + rr) * nside + (c0 + cc);
        }
    }
    __syncwarp();

    if (lane < 9) {
        int a = s_idx[warp * 9 + lane];
        int loc = a - base;
        float cx = ((loc % nside) + 0.5f) * s;
        float cy = ((loc / nside) + 0.5f) * s;
        const float half = 2.5f * s;
        const float area_a = (5.f * s) * (5.f * s);
        s_iou[warp * 9 + lane] = iou_eval(cx - half, cy - half, cx + half, cy + half,
                                          area_a, gx0, gy0, gx1, gy1);
        float l = cx - gx0, tt = cy - gy0, r = gx1 - cx, bo = gy1 - cy;
        float mn = fminf(fminf(l, tt), fminf(r, bo));
        s_ok[warp * 9 + lane] = (mn > EPSV) ? 1 : 0;
    }
    __syncthreads();

    if (threadIdx.x == 0) {
        float sum = 0.f;
#pragma unroll
        for (int k = 0; k < 27; k++) sum += s_iou[k];
        float mean = sum / 27.f;
        float ss = 0.f;
#pragma unroll
        for (int k = 0; k < 27; k++) { float d = s_iou[k] - mean; ss += d * d; }
        s_thr = mean + sqrtf(ss / 26.f);
    }
    __syncthreads();

    if (threadIdx.x < 27) {
        if (s_iou[threadIdx.x] > s_thr && s_ok[threadIdx.x]) {
            int idx = b * A_VAL + s_idx[threadIdx.x];
            atomicAdd(&g_pos_count[idx], 1);
            g_pos_gt[idx] = m;   // only consumed when count==1 (single writer then)
        }
    }
}

// ---------------------------------------------------------------------------
// Kernel 2 (MEGA, TMA + L2-persist edition): one block per 256 anchors.
//   Zero a 32KB smem buffer once.
//   Phase B: ONE thread issues 3 cp.async.bulk.L2::cache_hint (32K+32K+16K)
//            with a fractional evict_last policy (0.6): ~60% of the scores
//            lines camp in L2 across graph replays, so their rewrite next
//            replay is absorbed without a DRAM write-back — attacking the
//            ~3.9 TB/s DRAM write-drain floor that pins the loop at ~47us.
//   Phase A: assignment resolution (+ self-clean counter); labels/bbox use
//            __stcs (evict-first) so they DON'T pollute the persisting set.
//   Phase C: after wait_group 0 + syncthreads, scatter the sparse 1.0s.
// ---------------------------------------------------------------------------
__global__ void __launch_bounds__(256) mega_kernel(const float* __restrict__ gt_bboxes,
                                                   const int* __restrict__ gt_labels,
                                                   const int* __restrict__ bg_ptr,
                                                   float* __restrict__ out) {
    __shared__ __align__(16) float zbuf[ZBUF_BYTES / 4];
    __shared__ int s_pos_label[256];   // label if positive else -1

    const int tid = threadIdx.x;
    const int idx = blockIdx.x * 256 + tid;          // (b, anchor) flat
    const int b = idx / A_VAL;
    const int a = idx - b * A_VAL;

    // ---- zero the staging buffer (once per block) -------------------------
    {
        float4* zb = reinterpret_cast<float4*>(zbuf);
        const float4 z = make_float4(0.f, 0.f, 0.f, 0.f);
#pragma unroll
        for (int j = 0; j < (ZBUF_BYTES / 16) / 256; j++)   // 8 iterations
            zb[j * 256 + tid] = z;
    }
    __syncthreads();

    // ---- Phase B issue: bulk-zero this block's scores slab ----------------
    char* slab_bytes = reinterpret_cast<char*>(out + (size_t)BA_VAL * 5) +
                       (size_t)blockIdx.x * SLAB_BYTES;
    if (tid == 0) {
        asm volatile("fence.proxy.async.shared::cta;" ::: "memory");
        uint32_t saddr = smem_u32(zbuf);
        unsigned long long pol;
        asm("createpolicy.fractional.L2::evict_last.b64 %0, 0.6;" : "=l"(pol));
        asm volatile("cp.async.bulk.global.shared::cta.bulk_group.L2::cache_hint"
                     " [%0], [%1], %2, %3;"
                     :: "l"(slab_bytes),         "r"(saddr), "n"(32768), "l"(pol) : "memory");
        asm volatile("cp.async.bulk.global.shared::cta.bulk_group.L2::cache_hint"
                     " [%0], [%1], %2, %3;"
                     :: "l"(slab_bytes + 32768), "r"(saddr), "n"(32768), "l"(pol) : "memory");
        asm volatile("cp.async.bulk.global.shared::cta.bulk_group.L2::cache_hint"
                     " [%0], [%1], %2, %3;"
                     :: "l"(slab_bytes + 65536), "r"(saddr), "n"(16384), "l"(pol) : "memory");
        asm volatile("cp.async.bulk.commit_group;" ::: "memory");
    }

    // ---- Phase A (overlaps with in-flight TMA) ----------------------------
    int cnt = g_pos_count[idx];
    if (cnt != 0) g_pos_count[idx] = 0;              // self-clean for next launch
    int gt = 0;
    if (cnt == 1) {
        gt = g_pos_gt[idx];
    } else if (cnt > 1) {
        float cx, cy, half;
        anchor_geom(a, cx, cy, half);
        float ax0 = cx - half, ay0 = cy - half, ax1 = cx + half, ay1 = cy + half;
        float side = 2.f * half;
        float area_a = side * side;
        const float4* gb = reinterpret_cast<const float4*>(gt_bboxes) + b * M_VAL;
        float best = -1.f; int bm = 0;
        for (int mm = 0; mm < M_VAL; mm++) {
            float4 gg = __ldg(&gb[mm]);
            float iou = iou_eval(ax0, ay0, ax1, ay1, area_a, gg.x, gg.y, gg.z, gg.w);
            if (iou > best) { best = iou; bm = mm; }   // strict > : first max
        }
        gt = bm;
    }

    int label;
    if (cnt > 0) {
        label = gt_labels[b * M_VAL + gt];
        s_pos_label[tid] = label;
    } else {
        label = __ldg(bg_ptr);
        s_pos_label[tid] = -1;
    }
    __stcs(out + idx, (float)label);

    float4 gg = reinterpret_cast<const float4*>(gt_bboxes)[b * M_VAL + gt];
    __stcs(reinterpret_cast<float4*>(out + BA_VAL) + idx, gg);   // bboxes region

    // ---- wait for bulk zeros, then scatter sparse 1.0s --------------------
    if (tid == 0) {
        asm volatile("cp.async.bulk.wait_group 0;" ::: "memory");
    }
    __syncthreads();

    int pl = s_pos_label[tid];
    if (pl >= 0) {
        reinterpret_cast<float*>(slab_bytes)[tid * NC + pl] = 1.0f;
    }
}

// ---------------------------------------------------------------------------
extern "C" void kernel_launch(void* const* d_in, const int* in_sizes, int n_in,
                              void* d_out, int out_size) {
    const float* gt_bboxes = nullptr;
    const int*   gt_labels = nullptr;
    const float* pad_mask  = nullptr;
    const int*   bg_ptr    = nullptr;
    int seen_1024 = 0;
    for (int i = 0; i < n_in; i++) {
        int sz = in_sizes[i];
        if (sz == BM_VAL * 4)      gt_bboxes = (const float*)d_in[i];
        else if (sz == 1)          bg_ptr    = (const int*)d_in[i];
        else if (sz == BM_VAL) {
            if (seen_1024 == 0) gt_labels = (const int*)d_in[i];   // metadata order
            else                pad_mask  = (const float*)d_in[i];
            seen_1024++;
        }
    }
    float* out = (float*)d_out;

    topk_assign_kernel<<<BM_VAL, 96>>>(gt_bboxes, pad_mask);
    mega_kernel<<<BA_VAL / 256, 256>>>(gt_bboxes, gt_labels, bg_ptr, out);
}

// round 11
// speedup vs baseline: 1.0269x; 1.0269x over previous
#include <cuda_runtime.h>
#include <cstdint>

#define B_VAL 16
#define M_VAL 64
#define A_VAL 33600
#define BM_VAL (B_VAL * M_VAL)
#define BA_VAL (B_VAL * A_VAL)
#define NC 80
#define EPSV 1e-9f

#define SLAB_BYTES (256 * NC * 4)   // 81920 bytes of scores per block
#define ZBUF_BYTES 32768            // shared zero staging buffer

// Scratch: per-(b,anchor) positive count and (one) contributing gt index.
// Zero-initialized at module load; mega_kernel self-cleans g_pos_count after
// reading, so every launch (and graph replay) begins with a zeroed table.
__device__ int g_pos_count[BA_VAL];
__device__ int g_pos_gt[BA_VAL];

__device__ __forceinline__ uint32_t smem_u32(const void* p) {
    uint32_t a;
    asm("{ .reg .u64 t; cvta.to.shared.u64 t, %1; cvt.u32.u64 %0, t; }"
        : "=r"(a) : "l"(p));
    return a;
}

// ---------------------------------------------------------------------------
__device__ __forceinline__ void anchor_geom(int a, float& cx, float& cy, float& half) {
    int base, nside; float s;
    if (a < 25600)      { s = 8.f;  base = 0;     nside = 160; }
    else if (a < 32000) { s = 16.f; base = 25600; nside = 80;  }
    else                { s = 32.f; base = 32000; nside = 40;  }
    int loc = a - base;
    cx = ((loc % nside) + 0.5f) * s;
    cy = ((loc / nside) + 0.5f) * s;
    half = 2.5f * s;
}

__device__ __forceinline__ float iou_eval(float ax0, float ay0, float ax1, float ay1,
                                          float area_a,
                                          float gx0, float gy0, float gx1, float gy1) {
    float area_g = (gx1 - gx0) * (gy1 - gy0);
    float lx = fmaxf(gx0, ax0), ly = fmaxf(gy0, ay0);
    float rx = fminf(gx1, ax1), ry = fminf(gy1, ay1);
    float w = fmaxf(rx - lx, 0.f), h = fmaxf(ry - ly, 0.f);
    float ov = w * h;
    return ov / (area_g + area_a - ov + EPSV);
}

// ---------------------------------------------------------------------------
// Kernel 1 (warp-parallel, proven R8): ONE BLOCK (96 threads) per (b, m);
// warp = FPN level; 7x7 analytic window; 9 warp-min extractions on
// (d2_bits<<32)|p keys (lower-index tie-break preserved); canonical-order
// serial mean+std(ddof=1); center-in-gt; atomic scatter.
// Every block (valid or not) ends with griddepcontrol.launch_dependents so
// the PDL-launched mega kernel can pass its griddepcontrol.wait as soon as
// all scatters are flushed.
// ---------------------------------------------------------------------------
__global__ void __launch_bounds__(96) topk_assign_kernel(const float* __restrict__ gt_bboxes,
                                                         const float* __restrict__ pad_mask) {
    const int t = blockIdx.x;              // b*64 + m
    const bool valid = (pad_mask[t] > 0.f);

    if (valid) {
        const int b = t >> 6;
        const int m = t & 63;
        const int warp = threadIdx.x >> 5;     // level
        const int lane = threadIdx.x & 31;

        __shared__ int   s_idx[27];
        __shared__ float s_iou[27];
        __shared__ int   s_ok[27];
        __shared__ float s_thr;

        const float4 g = reinterpret_cast<const float4*>(gt_bboxes)[t];
        const float gx0 = g.x, gy0 = g.y, gx1 = g.z, gy1 = g.w;
        const float gcx = (gx0 + gx1) * 0.5f, gcy = (gy0 + gy1) * 0.5f;

        const int   base  = (warp == 0) ? 0     : (warp == 1) ? 25600 : 32000;
        const int   nside = (warp == 0) ? 160   : (warp == 1) ? 80    : 40;
        const float s     = (warp == 0) ? 8.f   : (warp == 1) ? 16.f  : 32.f;
        const float inv_s = (warp == 0) ? 0.125f : (warp == 1) ? 0.0625f : 0.03125f;

        int cn = (int)floorf(gcx * inv_s);
        int rn = (int)floorf(gcy * inv_s);
        int c0 = min(max(cn - 3, 0), nside - 7);
        int r0 = min(max(rn - 3, 0), nside - 7);

        auto cand_key = [&](int p) -> unsigned long long {
            int r = p / 7, c = p - r * 7;
            float cy = ((r0 + r) + 0.5f) * s;
            float cx = ((c0 + c) + 0.5f) * s;
            float dx = gcx - cx, dy = gcy - cy;
            float d2 = dx * dx + dy * dy;
            return ((unsigned long long)__float_as_uint(d2) << 32) | (unsigned)p;
        };

        const unsigned long long KMAX = ~0ULL;
        unsigned long long k0 = cand_key(lane);
        unsigned long long k1 = (lane + 32 < 49) ? cand_key(lane + 32) : KMAX;

#pragma unroll
        for (int round = 0; round < 9; round++) {
            unsigned long long local = (k0 < k1) ? k0 : k1;
            unsigned long long r = local;
#pragma unroll
            for (int off = 16; off > 0; off >>= 1) {
                unsigned long long o = __shfl_xor_sync(0xffffffffu, r, off);
                if (o < r) r = o;
            }
            if (local == r) {
                if (k0 == r) k0 = KMAX; else k1 = KMAX;
            }
            if (lane == 0) {
                int p = (int)(r & 0xffffffffu);
                int rr = p / 7, cc = p - rr * 7;
                s_idx[warp * 9 + round] = base + (r0 + rr) * nside + (c0 + cc);
            }
        }
        __syncwarp();

        if (lane < 9) {
            int a = s_idx[warp * 9 + lane];
            int loc = a - base;
            float cx = ((loc % nside) + 0.5f) * s;
            float cy = ((loc / nside) + 0.5f) * s;
            const float half = 2.5f * s;
            const float area_a = (5.f * s) * (5.f * s);
            s_iou[warp * 9 + lane] = iou_eval(cx - half, cy - half, cx + half, cy + half,
                                              area_a, gx0, gy0, gx1, gy1);
            float l = cx - gx0, tt = cy - gy0, r = gx1 - cx, bo = gy1 - cy;
            float mn = fminf(fminf(l, tt), fminf(r, bo));
            s_ok[warp * 9 + lane] = (mn > EPSV) ? 1 : 0;
        }
        __syncthreads();

        if (threadIdx.x == 0) {
            float sum = 0.f;
#pragma unroll
            for (int k = 0; k < 27; k++) sum += s_iou[k];
            float mean = sum / 27.f;
            float ss = 0.f;
#pragma unroll
            for (int k = 0; k < 27; k++) { float d = s_iou[k] - mean; ss += d * d; }
            s_thr = mean + sqrtf(ss / 26.f);
        }
        __syncthreads();

        if (threadIdx.x < 27) {
            if (s_iou[threadIdx.x] > s_thr && s_ok[threadIdx.x]) {
                int idx = b * A_VAL + s_idx[threadIdx.x];
                atomicAdd(&g_pos_count[idx], 1);
                g_pos_gt[idx] = m;   // only consumed when count==1 (single writer then)
            }
        }
        __syncthreads();
    }

    // PDL trigger: this block's scatter (if any) is done.
    asm volatile("griddepcontrol.launch_dependents;");
}

// ---------------------------------------------------------------------------
// Kernel 2 (MEGA, TMA + PDL edition): one block per 256 anchors. Launched
// with programmaticStreamSerialization, so blocks start WHILE topk runs:
//   - zero the 32KB smem staging buffer (independent of topk)
//   - issue 3 cp.async.bulk zeroing the block's 80KB scores slab (independent)
//   - griddepcontrol.wait  <-- only now consume topk's scatter tables
//   - Phase A: assignment resolution (+ self-clean counter); labels + bbox
//   - wait_group 0 + sync; Phase C: scatter sparse 1.0s
// ---------------------------------------------------------------------------
__global__ void __launch_bounds__(256) mega_kernel(const float* __restrict__ gt_bboxes,
                                                   const int* __restrict__ gt_labels,
                                                   const int* __restrict__ bg_ptr,
                                                   float* __restrict__ out) {
    __shared__ __align__(16) float zbuf[ZBUF_BYTES / 4];
    __shared__ int s_pos_label[256];   // label if positive else -1

    const int tid = threadIdx.x;
    const int idx = blockIdx.x * 256 + tid;          // (b, anchor) flat
    const int b = idx / A_VAL;
    const int a = idx - b * A_VAL;

    // ---- zero the staging buffer (once per block; no topk dependency) -----
    {
        float4* zb = reinterpret_cast<float4*>(zbuf);
        const float4 z = make_float4(0.f, 0.f, 0.f, 0.f);
#pragma unroll
        for (int j = 0; j < (ZBUF_BYTES / 16) / 256; j++)   // 8 iterations
            zb[j * 256 + tid] = z;
    }
    __syncthreads();

    // ---- Phase B issue: bulk-zero this block's scores slab (independent) --
    char* slab_bytes = reinterpret_cast<char*>(out + (size_t)BA_VAL * 5) +
                       (size_t)blockIdx.x * SLAB_BYTES;
    if (tid == 0) {
        asm volatile("fence.proxy.async.shared::cta;" ::: "memory");
        uint32_t saddr = smem_u32(zbuf);
        asm volatile("cp.async.bulk.global.shared::cta.bulk_group [%0], [%1], %2;"
                     :: "l"(slab_bytes),           "r"(saddr), "n"(32768) : "memory");
        asm volatile("cp.async.bulk.global.shared::cta.bulk_group [%0], [%1], %2;"
                     :: "l"(slab_bytes + 32768),   "r"(saddr), "n"(32768) : "memory");
        asm volatile("cp.async.bulk.global.shared::cta.bulk_group [%0], [%1], %2;"
                     :: "l"(slab_bytes + 65536),   "r"(saddr), "n"(16384) : "memory");
        asm volatile("cp.async.bulk.commit_group;" ::: "memory");
    }

    // ---- PDL: wait for topk's scatter tables before consuming them --------
    asm volatile("griddepcontrol.wait;" ::: "memory");

    // ---- Phase A ----------------------------------------------------------
    int cnt = g_pos_count[idx];
    if (cnt != 0) g_pos_count[idx] = 0;              // self-clean for next launch
    int gt = 0;
    if (cnt == 1) {
        gt = g_pos_gt[idx];
    } else if (cnt > 1) {
        float cx, cy, half;
        anchor_geom(a, cx, cy, half);
        float ax0 = cx - half, ay0 = cy - half, ax1 = cx + half, ay1 = cy + half;
        float side = 2.f * half;
        float area_a = side * side;
        const float4* gb = reinterpret_cast<const float4*>(gt_bboxes) + b * M_VAL;
        float best = -1.f; int bm = 0;
        for (int mm = 0; mm < M_VAL; mm++) {
            float4 gg = __ldg(&gb[mm]);
            float iou = iou_eval(ax0, ay0, ax1, ay1, area_a, gg.x, gg.y, gg.z, gg.w);
            if (iou > best) { best = iou; bm = mm; }   // strict > : first max
        }
        gt = bm;
    }

    int label;
    if (cnt > 0) {
        label = gt_labels[b * M_VAL + gt];
        s_pos_label[tid] = label;
    } else {
        label = __ldg(bg_ptr);
        s_pos_label[tid] = -1;
    }
    __stcs(out + idx, (float)label);

    float4 gg = reinterpret_cast<const float4*>(gt_bboxes)[b * M_VAL + gt];
    __stcs(reinterpret_cast<float4*>(out + BA_VAL) + idx, gg);   // bboxes region

    // ---- wait for bulk zeros, then scatter sparse 1.0s --------------------
    if (tid == 0) {
        asm volatile("cp.async.bulk.wait_group 0;" ::: "memory");
    }
    __syncthreads();

    int pl = s_pos_label[tid];
    if (pl >= 0) {
        reinterpret_cast<float*>(slab_bytes)[tid * NC + pl] = 1.0f;
    }
}

// ---------------------------------------------------------------------------
extern "C" void kernel_launch(void* const* d_in, const int* in_sizes, int n_in,
                              void* d_out, int out_size) {
    const float* gt_bboxes = nullptr;
    const int*   gt_labels = nullptr;
    const float* pad_mask  = nullptr;
    const int*   bg_ptr    = nullptr;
    int seen_1024 = 0;
    for (int i = 0; i < n_in; i++) {
        int sz = in_sizes[i];
        if (sz == BM_VAL * 4)      gt_bboxes = (const float*)d_in[i];
        else if (sz == 1)          bg_ptr    = (const int*)d_in[i];
        else if (sz == BM_VAL) {
            if (seen_1024 == 0) gt_labels = (const int*)d_in[i];   // metadata order
            else                pad_mask  = (const float*)d_in[i];
            seen_1024++;
        }
    }
    float* out = (float*)d_out;

    topk_assign_kernel<<<BM_VAL, 96>>>(gt_bboxes, pad_mask);

    // mega launched with Programmatic Stream Serialization: its blocks may
    // start while topk is still running; the device-side griddepcontrol.wait
    // provides the real dependency before the scatter tables are read.
    cudaLaunchConfig_t cfg = {};
    cfg.gridDim  = dim3(BA_VAL / 256);
    cfg.blockDim = dim3(256);
    cfg.dynamicSmemBytes = 0;
    cfg.stream = 0;
    cudaLaunchAttribute attr[1];
    attr[0].id = cudaLaunchAttributeProgrammaticStreamSerialization;
    attr[0].val.programmaticStreamSerializationAllowed = 1;
    cfg.attrs = attr;
    cfg.numAttrs = 1;
    cudaLaunchKernelEx(&cfg, mega_kernel, gt_bboxes, gt_labels, bg_ptr, out);
}